// round 1
// baseline (speedup 1.0000x reference)
#include <cuda_runtime.h>
#include <math.h>

#define NB 2
#define NT 4096
#define ND 1024
#define DH 32
#define KTOP 8
#define NSPLIT 4
#define TILE 128
#define TKA 16

// ---------------- scratch (device globals; no allocation) ----------------
__device__ float g_q[NB * NT * DH];
__device__ float g_k[NB * NT * DH];
__device__ float g_cv[NB * NT * NSPLIT * KTOP];
__device__ int   g_ci[NB * NT * NSPLIT * KTOP];
__device__ int   g_topk[NB * NT * KTOP];
__device__ float g_mean[NB * ND];

// =========================================================================
// Kernel 1: fused causal sim GEMM (fp32) + per-row running top-8.
// Grid: (32 row-tiles [reversed: heavy first], NSPLIT j-splits, NB batches)
// Block: 256 threads; 128x128 tile, 8x8 microtile, TK=16.
// =========================================================================
__global__ __launch_bounds__(256) void simtopk_kernel(const float* __restrict__ x)
{
    const int s   = blockIdx.y;
    const int tt  = (gridDim.x - 1) - blockIdx.x;   // heavy tiles first
    const int b   = blockIdx.z;
    const int t0  = tt * TILE;
    const int njt = tt + 1;                          // j-tiles 0..tt (incl. diagonal)
    const int jt_beg = (s * njt) / NSPLIT;
    const int jt_end = ((s + 1) * njt) / NSPLIT;

    __shared__ float stage[2 * TKA * TILE];          // 16KB: As|Bs, reused as merge buf
    __shared__ float tv[TILE][KTOP];
    __shared__ int   ti[TILE][KTOP];

    const int tid = threadIdx.x;
    for (int i = tid; i < TILE * KTOP; i += 256) ((float*)tv)[i] = -3.0e38f;
    __syncthreads();

    const int ty = tid >> 4, tx = tid & 15;
    const int lr = tid >> 1;            // 0..127 (row in tile)
    const int lk = (tid & 1) * 8;       // 0 or 8  (k offset)
    const float* xb = x + (size_t)b * NT * ND;

    for (int jt = jt_beg; jt < jt_end; ++jt) {
        const int j0 = jt * TILE;
        float acc[8][8];
#pragma unroll
        for (int i = 0; i < 8; ++i)
#pragma unroll
            for (int j = 0; j < 8; ++j) acc[i][j] = 0.0f;

        for (int kd = 0; kd < ND; kd += TKA) {
            const float4 a0 = *(const float4*)(xb + (size_t)(t0 + lr) * ND + kd + lk);
            const float4 a1 = *(const float4*)(xb + (size_t)(t0 + lr) * ND + kd + lk + 4);
            const float4 b0 = *(const float4*)(xb + (size_t)(j0 + lr) * ND + kd + lk);
            const float4 b1 = *(const float4*)(xb + (size_t)(j0 + lr) * ND + kd + lk + 4);
            float av[8] = {a0.x, a0.y, a0.z, a0.w, a1.x, a1.y, a1.z, a1.w};
            float bv[8] = {b0.x, b0.y, b0.z, b0.w, b1.x, b1.y, b1.z, b1.w};
            __syncthreads();            // previous-iter consumers / merge done
#pragma unroll
            for (int i = 0; i < 8; ++i) {
                stage[(lk + i) * TILE + lr] = av[i];
                stage[TKA * TILE + (lk + i) * TILE + lr] = bv[i];
            }
            __syncthreads();
            const float4* A4 = (const float4*)stage;                // [TKA][32]
            const float4* B4 = (const float4*)(stage + TKA * TILE); // [TKA][32]
#pragma unroll
            for (int k = 0; k < TKA; ++k) {
                const float4 av0 = A4[k * 32 + 2 * ty];
                const float4 av1 = A4[k * 32 + 2 * ty + 1];
                const float4 bv0 = B4[k * 32 + 2 * tx];
                const float4 bv1 = B4[k * 32 + 2 * tx + 1];
                const float ar[8] = {av0.x, av0.y, av0.z, av0.w, av1.x, av1.y, av1.z, av1.w};
                const float br[8] = {bv0.x, bv0.y, bv0.z, bv0.w, bv1.x, bv1.y, bv1.z, bv1.w};
#pragma unroll
                for (int i = 0; i < 8; ++i)
#pragma unroll
                    for (int j = 0; j < 8; ++j)
                        acc[i][j] = fmaf(ar[i], br[j], acc[i][j]);
            }
        }

        // ---- merge 128x128 scores into per-row top-8 (4 phases of 2 rows) ----
#pragma unroll 1
        for (int p = 0; p < 4; ++p) {
            __syncthreads();
#pragma unroll
            for (int q = 0; q < 2; ++q)
#pragma unroll
                for (int i = 0; i < 8; ++i)
                    stage[(2 * ty + q) * TILE + 8 * tx + i] = acc[2 * p + q][i];
            __syncthreads();
            if (tid < 32) {
                const int g = tid >> 1, q = tid & 1;
                const int row  = 8 * g + 2 * p + q;
                const int trow = t0 + row;
                float thr = tv[row][KTOP - 1];
                const float* bufr = stage + tid * TILE;
                for (int c = 0; c < TILE; ++c) {
                    const float v = bufr[c];
                    const int   j = j0 + c;
                    if (v > thr && j < trow) {          // strict causality j < t
                        int pos = KTOP - 1;
                        while (pos > 0 && tv[row][pos - 1] < v) {
                            tv[row][pos] = tv[row][pos - 1];
                            ti[row][pos] = ti[row][pos - 1];
                            --pos;
                        }
                        tv[row][pos] = v; ti[row][pos] = j;
                        thr = tv[row][KTOP - 1];
                    }
                }
            }
        }
    }

    __syncthreads();
    if (tid < TILE) {
        const int t = t0 + tid;
        const size_t base = (((size_t)b * NT + t) * NSPLIT + s) * KTOP;
#pragma unroll
        for (int i = 0; i < KTOP; ++i) { g_cv[base + i] = tv[tid][i]; g_ci[base + i] = ti[tid][i]; }
    }
}

// =========================================================================
// Kernel 2: merge the NSPLIT candidate lists per row -> final top-min(t,8).
// =========================================================================
__global__ void mergetopk_kernel()
{
    const int row = blockIdx.x * blockDim.x + threadIdx.x;
    if (row >= NB * NT) return;
    const int t = row & (NT - 1);
    float bv[KTOP]; int bi[KTOP];
#pragma unroll
    for (int i = 0; i < KTOP; ++i) { bv[i] = -3.4e38f; bi[i] = 0; }
    const size_t base = (size_t)row * NSPLIT * KTOP;
    for (int c = 0; c < NSPLIT * KTOP; ++c) {
        const float v = g_cv[base + c];
        if (v > bv[KTOP - 1]) {
            const int j = g_ci[base + c];
            int pos = KTOP - 1;
            while (pos > 0 && bv[pos - 1] < v) { bv[pos] = bv[pos - 1]; bi[pos] = bi[pos - 1]; --pos; }
            bv[pos] = v; bi[pos] = j;
        }
    }
    const int m = t < KTOP ? t : KTOP;
    for (int i = 0; i < m; ++i) g_topk[(size_t)row * KTOP + i] = bi[i];
}

// =========================================================================
// Kernel 3: q/k projection. out[8192 rows][64] = X @ [Wq;Wk]^T
// Grid: 128 blocks of 64 rows; block 256 threads, 64x64 tile, 4x4 micro.
// =========================================================================
__global__ __launch_bounds__(256) void qk_kernel(const float* __restrict__ x,
                                                 const float* __restrict__ Wq,
                                                 const float* __restrict__ Wk)
{
    const int row0 = blockIdx.x * 64;
    __shared__ float xs[16][64];
    __shared__ float ws[16][64];
    const int tid = threadIdx.x;
    const int ty = tid >> 4, tx = tid & 15;
    const int lr = tid >> 2;          // 0..63
    const int lk = (tid & 3) * 4;     // 0,4,8,12
    float acc[4][4];
#pragma unroll
    for (int i = 0; i < 4; ++i)
#pragma unroll
        for (int j = 0; j < 4; ++j) acc[i][j] = 0.0f;

    const float* Wrow = (lr < 32) ? (Wq + (size_t)lr * ND) : (Wk + (size_t)(lr - 32) * ND);
    for (int kd = 0; kd < ND; kd += 16) {
        const float4 xv = *(const float4*)(x + (size_t)(row0 + lr) * ND + kd + lk);
        const float4 wv = *(const float4*)(Wrow + kd + lk);
        __syncthreads();
        xs[lk + 0][lr] = xv.x; xs[lk + 1][lr] = xv.y; xs[lk + 2][lr] = xv.z; xs[lk + 3][lr] = xv.w;
        ws[lk + 0][lr] = wv.x; ws[lk + 1][lr] = wv.y; ws[lk + 2][lr] = wv.z; ws[lk + 3][lr] = wv.w;
        __syncthreads();
#pragma unroll
        for (int k = 0; k < 16; ++k) {
            const float4 a  = *(const float4*)&xs[k][4 * ty];
            const float4 w4 = *(const float4*)&ws[k][4 * tx];
            const float ar[4] = {a.x, a.y, a.z, a.w};
            const float br[4] = {w4.x, w4.y, w4.z, w4.w};
#pragma unroll
            for (int i = 0; i < 4; ++i)
#pragma unroll
                for (int j = 0; j < 4; ++j)
                    acc[i][j] = fmaf(ar[i], br[j], acc[i][j]);
        }
    }
#pragma unroll
    for (int i = 0; i < 4; ++i) {
        const int rw = row0 + 4 * ty + i;
#pragma unroll
        for (int j = 0; j < 4; ++j) {
            const int h = 4 * tx + j;
            if (h < 32) g_q[(size_t)rw * DH + h] = acc[i][j];
            else        g_k[(size_t)rw * DH + (h - 32)] = acc[i][j];
        }
    }
}

// =========================================================================
// Kernel 4: per-batch column mean of x (for the t==0 uniform-softmax case).
// Grid: (8 col-chunks, NB); block 256 = 8 row-groups x 32 lanes.
// =========================================================================
__global__ void mean_kernel(const float* __restrict__ x)
{
    const int b    = blockIdx.y;
    const int lane = threadIdx.x & 31;
    const int g    = threadIdx.x >> 5;
    const int c4   = blockIdx.x * 32 + lane;       // float4 column 0..255
    const float* xb = x + (size_t)b * NT * ND;
    float4 acc = {0.f, 0.f, 0.f, 0.f};
    for (int r = g; r < NT; r += 8) {
        const float4 v = *(const float4*)(xb + (size_t)r * ND + 4 * c4);
        acc.x += v.x; acc.y += v.y; acc.z += v.z; acc.w += v.w;
    }
    __shared__ float4 red[8][32];
    red[g][lane] = acc;
    __syncthreads();
    if (g == 0) {
        float4 sm = red[0][lane];
        for (int q = 1; q < 8; ++q) {
            const float4 v = red[q][lane];
            sm.x += v.x; sm.y += v.y; sm.z += v.z; sm.w += v.w;
        }
        const float inv = 1.0f / (float)NT;
        sm.x *= inv; sm.y *= inv; sm.z *= inv; sm.w *= inv;
        *(float4*)(g_mean + b * ND + 4 * c4) = sm;
    }
}

// =========================================================================
// Kernel 5: scores on selected neighbors, softmax, gather, blend, GELU.
// Grid: 8192 blocks (one per row), 256 threads (4 floats of D each).
// =========================================================================
__global__ __launch_bounds__(256) void out_kernel(const float* __restrict__ x,
                                                  const float* __restrict__ gain,
                                                  const float* __restrict__ bias,
                                                  const float* __restrict__ p_lm,
                                                  const float* __restrict__ p_ls,
                                                  float* __restrict__ out)
{
    const int row = blockIdx.x;
    const int b = row >> 12;
    const int t = row & (NT - 1);
    const int tid = threadIdx.x;

    const float mix   = 1.0f / (1.0f + expf(-p_lm[0]));
    const float scale = log1pf(expf(p_ls[0])) + 0.01f;

    __shared__ float w[KTOP];
    __shared__ int   jj[KTOP];
    const int m = t < KTOP ? t : KTOP;

    if (m > 0) {
        if (tid < m) {
            const int j = g_topk[(size_t)row * KTOP + tid];
            jj[tid] = j;
            const float* qv = g_q + (size_t)row * DH;
            const float* kv = g_k + ((size_t)b * NT + j) * DH;
            float sc = 0.0f;
#pragma unroll
            for (int h = 0; h < DH; ++h) sc = fmaf(qv[h], kv[h], sc);
            w[tid] = sc * 0.17677669529663687f;    // 1/sqrt(32)
        }
        __syncthreads();
        if (tid == 0) {
            float mx = w[0];
            for (int i = 1; i < m; ++i) mx = fmaxf(mx, w[i]);
            float sum = 0.0f;
            for (int i = 0; i < m; ++i) { const float e = expf(w[i] - mx); w[i] = e; sum += e; }
            const float inv = 1.0f / sum;
            for (int i = 0; i < m; ++i) w[i] *= inv;
        }
        __syncthreads();
    }

    const int d0 = 4 * tid;
    float4 msg;
    if (m > 0) {
        float4 a = {0.f, 0.f, 0.f, 0.f};
        for (int i = 0; i < m; ++i) {
            const float wi = w[i];
            const float4 xv = *(const float4*)(x + ((size_t)b * NT + jj[i]) * ND + d0);
            a.x = fmaf(wi, xv.x, a.x);
            a.y = fmaf(wi, xv.y, a.y);
            a.z = fmaf(wi, xv.z, a.z);
            a.w = fmaf(wi, xv.w, a.w);
        }
        msg = a;
    } else {
        msg = *(const float4*)(g_mean + b * ND + d0);   // ref: uniform softmax over all T
    }

    const float4 xt = *(const float4*)(x + (size_t)row * ND + d0);
    const float4 gn = *(const float4*)(gain + d0);
    const float4 bs = *(const float4*)(bias + d0);
    const float om = 1.0f - mix;
    float4 o;
#define GEL(c) { float z = mix * xt.c + om * msg.c;                         \
                 z = fmaf(z, gn.c, bs.c);                                   \
                 o.c = 0.5f * z * (1.0f + erff(z * 0.7071067811865476f)) * scale; }
    GEL(x) GEL(y) GEL(z) GEL(w)
#undef GEL
    *(float4*)(out + (size_t)row * ND + d0) = o;
}

// =========================================================================
extern "C" void kernel_launch(void* const* d_in, const int* in_sizes, int n_in,
                              void* d_out, int out_size)
{
    (void)in_sizes; (void)n_in; (void)out_size;
    const float* x    = (const float*)d_in[0];
    const float* Wq   = (const float*)d_in[1];
    const float* Wk   = (const float*)d_in[2];
    const float* gain = (const float*)d_in[3];
    const float* bias = (const float*)d_in[4];
    const float* lm   = (const float*)d_in[5];
    const float* ls   = (const float*)d_in[6];
    float* out = (float*)d_out;

    simtopk_kernel<<<dim3(NT / TILE, NSPLIT, NB), 256>>>(x);
    mergetopk_kernel<<<(NB * NT + 255) / 256, 256>>>();
    qk_kernel<<<NB * NT / 64, 256>>>(x, Wq, Wk);
    mean_kernel<<<dim3(8, NB), 256>>>(x);
    out_kernel<<<NB * NT, 256>>>(x, gain, bias, lm, ls, out);
}

// round 3
// speedup vs baseline: 5.7629x; 5.7629x over previous
#include <cuda_runtime.h>
#include <cuda_bf16.h>
#include <math.h>
#include <stdint.h>

#define NB 2
#define NT 4096
#define ND 1024
#define DH 32
#define KTOP 8
#define TILE 128
#define KC 32            // bf16 K-chunk: 32 elems = 64 bytes/row
#define NCH (ND / KC)    // 32 chunks
#define NCPT 12          // candidates kept per tile (screening margin)
#define NCAND 12         // merged candidates per row

// ---------------- scratch (device globals; no allocation) ----------------
__device__ __nv_bfloat16 g_xb[NB * NT * ND];
__device__ float g_q[NB * NT * DH];
__device__ float g_k[NB * NT * DH];
__device__ float g_cv[NB * NT * 32 * NCPT];
__device__ int   g_ci[NB * NT * 32 * NCPT];
__device__ int   g_cand[NB * NT * NCAND];
__device__ int   g_cnt[NB * NT];
__device__ int   g_topk[NB * NT * KTOP];
__device__ float g_meanp[16 * NB * ND];
__device__ float g_mean[NB * ND];

// ======================= helpers ===========================
__device__ __forceinline__ uint32_t smem_u32(const void* p) {
    uint32_t a;
    asm("{ .reg .u64 t; cvta.to.shared.u64 t, %1; cvt.u32.u64 %0, t; }" : "=r"(a) : "l"(p));
    return a;
}
#define SW64(o) ((o) ^ (((o) >> 3) & 0x30))

__device__ __forceinline__ void ldmatrix_x4(uint32_t& r0, uint32_t& r1, uint32_t& r2, uint32_t& r3,
                                            uint32_t addr) {
    asm volatile("ldmatrix.sync.aligned.m8n8.x4.shared.b16 {%0,%1,%2,%3}, [%4];"
                 : "=r"(r0), "=r"(r1), "=r"(r2), "=r"(r3) : "r"(addr));
}
__device__ __forceinline__ void mma_bf16(float& c0, float& c1, float& c2, float& c3,
                                         uint32_t a0, uint32_t a1, uint32_t a2, uint32_t a3,
                                         uint32_t b0, uint32_t b1) {
    asm volatile("mma.sync.aligned.m16n8k16.row.col.f32.bf16.bf16.f32 "
                 "{%0,%1,%2,%3}, {%4,%5,%6,%7}, {%8,%9}, {%0,%1,%2,%3};"
                 : "+f"(c0), "+f"(c1), "+f"(c2), "+f"(c3)
                 : "r"(a0), "r"(a1), "r"(a2), "r"(a3), "r"(b0), "r"(b1));
}

// ========================= Kernel: x -> bf16 ============================
__global__ __launch_bounds__(256) void xcvt_kernel(const float* __restrict__ x)
{
    const size_t i = (size_t)blockIdx.x * 256 + threadIdx.x;   // float4 index
    const float4 v = ((const float4*)x)[i];
    __nv_bfloat162* o = (__nv_bfloat162*)g_xb;
    o[2 * i + 0] = __floats2bfloat162_rn(v.x, v.y);
    o[2 * i + 1] = __floats2bfloat162_rn(v.z, v.w);
}

// =============== Kernel: HMMA sim GEMM + per-tile top-12 =============
// One CTA per (tt, jt) pair per batch. 256 threads = 8 warps (2m x 4n),
// warp tile 64x32, mma m16n8k16 bf16, fp32 accum.
__global__ __launch_bounds__(256) void simmma_kernel()
{
    __shared__ __align__(128) char sm[32768];   // A0|B0|A1|B1 (8KB each); reused for scores
    const int tid = threadIdx.x;
    const int w = tid >> 5, l = tid & 31;
    const int b = blockIdx.y;

    // decode job -> (tt, jt)
    const int id = blockIdx.x;
    int tt = (int)((sqrtf(8.0f * (float)id + 1.0f) - 1.0f) * 0.5f);
    while ((tt + 1) * (tt + 2) / 2 <= id) ++tt;
    while (tt * (tt + 1) / 2 > id) --tt;
    const int jt = id - tt * (tt + 1) / 2;
    const int t0 = tt * TILE, j0 = jt * TILE;

    const int wm = (w >> 2) * 64;     // warp row offset (0 or 64)
    const int wn = (w & 3) * 32;      // warp col offset

    // ---- precompute swizzled ldmatrix byte offsets (within 8KB buffer) ----
    const int lr8 = l & 7;
    const int lb3 = (l >> 3) & 1;
    const int lb4 = (l >> 4) & 1;
    uint32_t aoff[4], boff[2];
#pragma unroll
    for (int mi = 0; mi < 4; ++mi) {
        const uint32_t row = (uint32_t)(wm + mi * 16 + lr8 + lb3 * 8);
        const uint32_t o = row * 64 + (uint32_t)lb4 * 16;
        aoff[mi] = SW64(o);
    }
#pragma unroll
    for (int n2 = 0; n2 < 2; ++n2) {
        const uint32_t row = (uint32_t)(wn + n2 * 16 + lb4 * 8 + lr8);
        const uint32_t o = row * 64 + (uint32_t)lb3 * 16;
        boff[n2] = SW64(o);
    }

    float acc[4][4][4];
#pragma unroll
    for (int mi = 0; mi < 4; ++mi)
#pragma unroll
        for (int ni = 0; ni < 4; ++ni)
#pragma unroll
            for (int q = 0; q < 4; ++q) acc[mi][ni][q] = 0.0f;

    const __nv_bfloat16* xb = g_xb + (size_t)b * NT * ND;
    const int r  = tid >> 1;              // row 0..127
    const int u0 = (tid & 1) * 2;         // 16B unit within 64B row
    const uint32_t sb = smem_u32(sm);

    uint4 av[2], bv[2];
#define GLOAD(cc) do {                                                          \
    const __nv_bfloat16* ap = xb + (size_t)(t0 + r) * ND + (cc) * KC + u0 * 8;  \
    const __nv_bfloat16* bp = xb + (size_t)(j0 + r) * ND + (cc) * KC + u0 * 8;  \
    av[0] = *(const uint4*)(ap);     av[1] = *(const uint4*)(ap + 8);           \
    bv[0] = *(const uint4*)(bp);     bv[1] = *(const uint4*)(bp + 8);           \
} while (0)
#define SSTORE(p) do {                                                          \
    const uint32_t o0 = SW64((uint32_t)(r * 64 + u0 * 16));                     \
    const uint32_t o1 = SW64((uint32_t)(r * 64 + (u0 + 1) * 16));               \
    char* ab = sm + (p) * 16384;                                                \
    *(uint4*)(ab + o0) = av[0];  *(uint4*)(ab + o1) = av[1];                    \
    *(uint4*)(ab + 8192 + o0) = bv[0];  *(uint4*)(ab + 8192 + o1) = bv[1];      \
} while (0)

    GLOAD(0);
    SSTORE(0);
    for (int c = 0; c < NCH; ++c) {
        const int p = c & 1;
        if (c + 1 < NCH) GLOAD(c + 1);
        __syncthreads();
        const uint32_t aB = sb + p * 16384;
        const uint32_t bB = aB + 8192;
#pragma unroll
        for (int ks = 0; ks < 2; ++ks) {
            uint32_t af[4][4], bf[2][4];
#pragma unroll
            for (int mi = 0; mi < 4; ++mi)
                ldmatrix_x4(af[mi][0], af[mi][1], af[mi][2], af[mi][3],
                            aB + (aoff[mi] ^ (ks * 32)));
#pragma unroll
            for (int n2 = 0; n2 < 2; ++n2)
                ldmatrix_x4(bf[n2][0], bf[n2][1], bf[n2][2], bf[n2][3],
                            bB + (boff[n2] ^ (ks * 32)));
#pragma unroll
            for (int mi = 0; mi < 4; ++mi)
#pragma unroll
                for (int ni = 0; ni < 4; ++ni)
                    mma_bf16(acc[mi][ni][0], acc[mi][ni][1], acc[mi][ni][2], acc[mi][ni][3],
                             af[mi][0], af[mi][1], af[mi][2], af[mi][3],
                             bf[ni >> 1][(ni & 1) * 2], bf[ni >> 1][(ni & 1) * 2 + 1]);
        }
        if (c + 1 < NCH) SSTORE(p ^ 1);
    }

    // ---- epilogue: 4 column-chunks of 32, stage to smem, running top-12 ----
    // accum fragment map: rows wm+mi*16+{g,g+8}, cols wn+ni*8+tg*2+{0,1}
    const int g  = l >> 2;
    const int tg = l & 3;
    float* sc = (float*)sm;                 // [128][34] per chunk (17408 B)
    float tv[NCPT]; int tj[NCPT];
#pragma unroll
    for (int i = 0; i < NCPT; ++i) { tv[i] = -3.0e38f; tj[i] = 0; }
    const int myt = t0 + tid;               // row this thread scans (tid < 128)

#pragma unroll 1
    for (int ch = 0; ch < 4; ++ch) {
        __syncthreads();                    // prior reads (bufs or prev chunk) done
        if ((w & 3) == ch) {
#pragma unroll
            for (int mi = 0; mi < 4; ++mi)
#pragma unroll
                for (int ni = 0; ni < 4; ++ni) {
                    const int colw = ni * 8 + tg * 2;
                    float* p0 = sc + (wm + mi * 16 + g) * 34 + colw;
                    float* p1 = sc + (wm + mi * 16 + g + 8) * 34 + colw;
                    p0[0] = acc[mi][ni][0]; p0[1] = acc[mi][ni][1];
                    p1[0] = acc[mi][ni][2]; p1[1] = acc[mi][ni][3];
                }
        }
        __syncthreads();
        if (tid < 128) {
            const float* rowp = sc + tid * 34;
            const int jb = j0 + ch * 32;
#pragma unroll 1
            for (int cix = 0; cix < 32; ++cix) {
                const float v = rowp[cix];
                const int   j = jb + cix;
                if (v > tv[NCPT - 1] && j < myt) {
                    tv[NCPT - 1] = v; tj[NCPT - 1] = j;
#pragma unroll
                    for (int q = NCPT - 1; q > 0; --q) {
                        if (tv[q] > tv[q - 1]) {
                            const float tf = tv[q]; tv[q] = tv[q - 1]; tv[q - 1] = tf;
                            const int   ii = tj[q]; tj[q] = tj[q - 1]; tj[q - 1] = ii;
                        }
                    }
                }
            }
        }
    }

    if (tid < 128) {
        const size_t base = ((size_t)(b * NT + myt) * 32 + jt) * NCPT;
#pragma unroll
        for (int i = 0; i < NCPT; ++i) { g_cv[base + i] = tv[i]; g_ci[base + i] = tj[i]; }
    }
}

// ============ Kernel: merge per-tile lists -> top-12 candidates =========
__global__ void merge_kernel()
{
    const int row = blockIdx.x * blockDim.x + threadIdx.x;
    if (row >= NB * NT) return;
    const int t  = row & (NT - 1);
    const int nl = (t >> 7) + 1;
    float bv[NCAND]; int bi[NCAND];
    for (int i = 0; i < NCAND; ++i) { bv[i] = -3.0e38f; bi[i] = 0; }
    for (int l = 0; l < nl; ++l) {
        const size_t base = ((size_t)row * 32 + l) * NCPT;
        for (int i = 0; i < NCPT; ++i) {
            const float v = g_cv[base + i];
            if (v <= bv[NCAND - 1]) break;          // lists sorted desc
            const int j = g_ci[base + i];
            int pos = NCAND - 1;
            while (pos > 0 && bv[pos - 1] < v) {
                bv[pos] = bv[pos - 1]; bi[pos] = bi[pos - 1]; --pos;
            }
            bv[pos] = v; bi[pos] = j;
        }
    }
    int m = 0;
    for (int i = 0; i < NCAND; ++i) {
        if (bv[i] > -1.0e30f) { g_cand[(size_t)row * NCAND + i] = bi[i]; ++m; }
    }
    g_cnt[row] = m;
}

// ======= Kernel: exact fp32 re-rank of candidates -> final top-8 ========
__global__ __launch_bounds__(256) void rerank_kernel(const float* __restrict__ x)
{
    const int row = blockIdx.x;
    const int b = row >> 12, t = row & (NT - 1);
    const int tid = threadIdx.x, wid = tid >> 5, lane = tid & 31;
    const int m = g_cnt[row];
    __shared__ float sval[NCAND];
    __shared__ int   scand[NCAND];
    if (m == 0) return;
    if (tid < m) scand[tid] = g_cand[(size_t)row * NCAND + tid];
    __syncthreads();

    const float4* qa = (const float4*)(x + (size_t)(b * NT + t) * ND);
#pragma unroll 1
    for (int cc = wid; cc < m; cc += 8) {
        const int j = scand[cc];
        const float4* ka = (const float4*)(x + (size_t)(b * NT + j) * ND);
        float s = 0.0f;
#pragma unroll
        for (int i = 0; i < 8; ++i) {
            const float4 q4 = qa[i * 32 + lane];
            const float4 k4 = ka[i * 32 + lane];
            s = fmaf(q4.x, k4.x, s); s = fmaf(q4.y, k4.y, s);
            s = fmaf(q4.z, k4.z, s); s = fmaf(q4.w, k4.w, s);
        }
#pragma unroll
        for (int o = 16; o > 0; o >>= 1) s += __shfl_xor_sync(0xffffffffu, s, o);
        if (lane == 0) sval[cc] = s;
    }
    __syncthreads();
    if (tid == 0) {
        const int kk = m < KTOP ? m : KTOP;
        bool usedf[NCAND];
        for (int i = 0; i < m; ++i) usedf[i] = false;
        for (int rr = 0; rr < kk; ++rr) {
            int best = -1; float bvv = -3.4e38f;
            for (int i = 0; i < m; ++i)
                if (!usedf[i] && sval[i] > bvv) { bvv = sval[i]; best = i; }
            usedf[best] = true;
            g_topk[(size_t)row * KTOP + rr] = scand[best];
        }
    }
}

// ===================== Kernel: q/k projection ===========================
__global__ __launch_bounds__(256) void qk_kernel(const float* __restrict__ x,
                                                 const float* __restrict__ Wq,
                                                 const float* __restrict__ Wk)
{
    const int row0 = blockIdx.x * 64;
    __shared__ float xs[16][64];
    __shared__ float ws[16][64];
    const int tid = threadIdx.x;
    const int ty = tid >> 4, tx = tid & 15;
    const int lr = tid >> 2;
    const int lk = (tid & 3) * 4;
    float acc[4][4];
#pragma unroll
    for (int i = 0; i < 4; ++i)
#pragma unroll
        for (int j = 0; j < 4; ++j) acc[i][j] = 0.0f;

    const float* Wrow = (lr < 32) ? (Wq + (size_t)lr * ND) : (Wk + (size_t)(lr - 32) * ND);
    for (int kd = 0; kd < ND; kd += 16) {
        const float4 xv = *(const float4*)(x + (size_t)(row0 + lr) * ND + kd + lk);
        const float4 wv = *(const float4*)(Wrow + kd + lk);
        __syncthreads();
        xs[lk + 0][lr] = xv.x; xs[lk + 1][lr] = xv.y; xs[lk + 2][lr] = xv.z; xs[lk + 3][lr] = xv.w;
        ws[lk + 0][lr] = wv.x; ws[lk + 1][lr] = wv.y; ws[lk + 2][lr] = wv.z; ws[lk + 3][lr] = wv.w;
        __syncthreads();
#pragma unroll
        for (int k = 0; k < 16; ++k) {
            const float4 a  = *(const float4*)&xs[k][4 * ty];
            const float4 w4 = *(const float4*)&ws[k][4 * tx];
            const float ar[4] = {a.x, a.y, a.z, a.w};
            const float br[4] = {w4.x, w4.y, w4.z, w4.w};
#pragma unroll
            for (int i = 0; i < 4; ++i)
#pragma unroll
                for (int j = 0; j < 4; ++j)
                    acc[i][j] = fmaf(ar[i], br[j], acc[i][j]);
        }
    }
#pragma unroll
    for (int i = 0; i < 4; ++i) {
        const int rw = row0 + 4 * ty + i;
#pragma unroll
        for (int j = 0; j < 4; ++j) {
            const int h = 4 * tx + j;
            if (h < 32) g_q[(size_t)rw * DH + h] = acc[i][j];
            else        g_k[(size_t)rw * DH + (h - 32)] = acc[i][j];
        }
    }
}

// ============== Kernels: deterministic 2-pass column mean ===============
__global__ void mean1_kernel(const float* __restrict__ x)
{
    const int b = blockIdx.y, z = blockIdx.z;
    const int lane = threadIdx.x & 31, g = threadIdx.x >> 5;
    const int c4 = blockIdx.x * 32 + lane;
    const float* xb = x + (size_t)b * NT * ND;
    float4 acc = {0.f, 0.f, 0.f, 0.f};
    for (int r = z * 256 + g; r < z * 256 + 256; r += 8) {
        const float4 v = *(const float4*)(xb + (size_t)r * ND + 4 * c4);
        acc.x += v.x; acc.y += v.y; acc.z += v.z; acc.w += v.w;
    }
    __shared__ float4 red[8][32];
    red[g][lane] = acc;
    __syncthreads();
    if (g == 0) {
        float4 sm = red[0][lane];
        for (int q = 1; q < 8; ++q) {
            const float4 v = red[q][lane];
            sm.x += v.x; sm.y += v.y; sm.z += v.z; sm.w += v.w;
        }
        *(float4*)(g_meanp + ((size_t)z * NB + b) * ND + 4 * c4) = sm;
    }
}
__global__ void mean2_kernel()
{
    const int idx = blockIdx.x * blockDim.x + threadIdx.x;
    if (idx >= NB * ND) return;
    const int b = idx / ND, d = idx % ND;
    float s = 0.0f;
    for (int z = 0; z < 16; ++z) s += g_meanp[((size_t)z * NB + b) * ND + d];
    g_mean[b * ND + d] = s * (1.0f / (float)NT);
}

// ========== Kernel: scores, softmax, gather, blend, GELU ================
__global__ __launch_bounds__(256) void out_kernel(const float* __restrict__ x,
                                                  const float* __restrict__ gain,
                                                  const float* __restrict__ bias,
                                                  const float* __restrict__ p_lm,
                                                  const float* __restrict__ p_ls,
                                                  float* __restrict__ out)
{
    const int row = blockIdx.x;
    const int b = row >> 12;
    const int t = row & (NT - 1);
    const int tid = threadIdx.x;

    const float mix   = 1.0f / (1.0f + expf(-p_lm[0]));
    const float scale = log1pf(expf(p_ls[0])) + 0.01f;

    __shared__ float w[KTOP];
    __shared__ int   jj[KTOP];
    const int m = t < KTOP ? t : KTOP;

    if (m > 0) {
        if (tid < m) {
            const int j = g_topk[(size_t)row * KTOP + tid];
            jj[tid] = j;
            const float* qv = g_q + (size_t)row * DH;
            const float* kv = g_k + ((size_t)b * NT + j) * DH;
            float sc = 0.0f;
#pragma unroll
            for (int h = 0; h < DH; ++h) sc = fmaf(qv[h], kv[h], sc);
            w[tid] = sc * 0.17677669529663687f;
        }
        __syncthreads();
        if (tid == 0) {
            float mx = w[0];
            for (int i = 1; i < m; ++i) mx = fmaxf(mx, w[i]);
            float sum = 0.0f;
            for (int i = 0; i < m; ++i) { const float e = expf(w[i] - mx); w[i] = e; sum += e; }
            const float inv = 1.0f / sum;
            for (int i = 0; i < m; ++i) w[i] *= inv;
        }
        __syncthreads();
    }

    const int d0 = 4 * tid;
    float4 msg;
    if (m > 0) {
        float4 a = {0.f, 0.f, 0.f, 0.f};
        for (int i = 0; i < m; ++i) {
            const float wi = w[i];
            const float4 xv = *(const float4*)(x + ((size_t)b * NT + jj[i]) * ND + d0);
            a.x = fmaf(wi, xv.x, a.x);
            a.y = fmaf(wi, xv.y, a.y);
            a.z = fmaf(wi, xv.z, a.z);
            a.w = fmaf(wi, xv.w, a.w);
        }
        msg = a;
    } else {
        msg = *(const float4*)(g_mean + b * ND + d0);
    }

    const float4 xt = *(const float4*)(x + (size_t)row * ND + d0);
    const float4 gn = *(const float4*)(gain + d0);
    const float4 bs = *(const float4*)(bias + d0);
    const float om = 1.0f - mix;
    float4 o;
#define GEL(c) { float z = mix * xt.c + om * msg.c;                         \
                 z = fmaf(z, gn.c, bs.c);                                   \
                 o.c = 0.5f * z * (1.0f + erff(z * 0.7071067811865476f)) * scale; }
    GEL(x) GEL(y) GEL(z) GEL(w)
#undef GEL
    *(float4*)(out + (size_t)row * ND + d0) = o;
}

// =========================================================================
extern "C" void kernel_launch(void* const* d_in, const int* in_sizes, int n_in,
                              void* d_out, int out_size)
{
    (void)in_sizes; (void)n_in; (void)out_size;
    const float* x    = (const float*)d_in[0];
    const float* Wq   = (const float*)d_in[1];
    const float* Wk   = (const float*)d_in[2];
    const float* gain = (const float*)d_in[3];
    const float* bias = (const float*)d_in[4];
    const float* lm   = (const float*)d_in[5];
    const float* ls   = (const float*)d_in[6];
    float* out = (float*)d_out;

    xcvt_kernel<<<NB * NT * ND / 4 / 256, 256>>>(x);
    qk_kernel<<<NB * NT / 64, 256>>>(x, Wq, Wk);
    mean1_kernel<<<dim3(8, NB, 16), 256>>>(x);
    simmma_kernel<<<dim3(528, NB), 256>>>();
    mean2_kernel<<<(NB * ND + 255) / 256, 256>>>();
    merge_kernel<<<(NB * NT + 255) / 256, 256>>>();
    rerank_kernel<<<NB * NT, 256>>>(x);
    out_kernel<<<NB * NT, 256>>>(x, gain, bias, lm, ls, out);
}

// round 5
// speedup vs baseline: 6.7354x; 1.1688x over previous
#include <cuda_runtime.h>
#include <cuda_bf16.h>
#include <math.h>
#include <stdint.h>

#define NB 2
#define NT 4096
#define ND 1024
#define DH 32
#define KTOP 8
#define TILE 128
#define KC 32            // bf16 K-chunk: 32 elems = 64 bytes/row
#define NCH (ND / KC)    // 32 chunks
#define NCPT 12          // candidates kept per tile (screening margin)
#define NCAND 12         // merged candidates per row

// ---------------- scratch (device globals; no allocation) ----------------
__device__ __nv_bfloat16 g_xb[NB * NT * ND];
__device__ float g_q[NB * NT * DH];
__device__ float g_k[NB * NT * DH];
__device__ float g_cv[NB * NT * 32 * NCPT];
__device__ int   g_ci[NB * NT * 32 * NCPT];
__device__ int   g_cand[NB * NT * NCAND];
__device__ int   g_cnt[NB * NT];
__device__ float g_meanp[16 * NB * ND];
__device__ float g_mean[NB * ND];

// ======================= helpers ===========================
__device__ __forceinline__ uint32_t smem_u32(const void* p) {
    uint32_t a;
    asm("{ .reg .u64 t; cvta.to.shared.u64 t, %1; cvt.u32.u64 %0, t; }" : "=r"(a) : "l"(p));
    return a;
}
#define SW64(o) ((o) ^ (((o) >> 3) & 0x30))
#define CP_ASYNC16(dst, src) \
    asm volatile("cp.async.cg.shared.global [%0], [%1], 16;" :: "r"(dst), "l"(src))
#define CP_COMMIT() asm volatile("cp.async.commit_group;" ::: "memory")
#define CP_WAIT(n)  asm volatile("cp.async.wait_group %0;" :: "n"(n) : "memory")

__device__ __forceinline__ void ldmatrix_x4(uint32_t& r0, uint32_t& r1, uint32_t& r2, uint32_t& r3,
                                            uint32_t addr) {
    asm volatile("ldmatrix.sync.aligned.m8n8.x4.shared.b16 {%0,%1,%2,%3}, [%4];"
                 : "=r"(r0), "=r"(r1), "=r"(r2), "=r"(r3) : "r"(addr));
}
__device__ __forceinline__ void mma_bf16(float& c0, float& c1, float& c2, float& c3,
                                         uint32_t a0, uint32_t a1, uint32_t a2, uint32_t a3,
                                         uint32_t b0, uint32_t b1) {
    asm volatile("mma.sync.aligned.m16n8k16.row.col.f32.bf16.bf16.f32 "
                 "{%0,%1,%2,%3}, {%4,%5,%6,%7}, {%8,%9}, {%0,%1,%2,%3};"
                 : "+f"(c0), "+f"(c1), "+f"(c2), "+f"(c3)
                 : "r"(a0), "r"(a1), "r"(a2), "r"(a3), "r"(b0), "r"(b1));
}

// ========================= Kernel: x -> bf16 ============================
__global__ __launch_bounds__(256) void xcvt_kernel(const float* __restrict__ x)
{
    const size_t i = (size_t)blockIdx.x * 256 + threadIdx.x;   // float4 index
    const float4 v = ((const float4*)x)[i];
    __nv_bfloat162* o = (__nv_bfloat162*)g_xb;
    o[2 * i + 0] = __floats2bfloat162_rn(v.x, v.y);
    o[2 * i + 1] = __floats2bfloat162_rn(v.z, v.w);
}

// =============== Kernel: HMMA sim GEMM + per-tile top-12 =============
// One CTA per (tt, jt) pair per batch. 256 threads = 8 warps (2m x 4n),
// warp tile 64x32, mma m16n8k16 bf16, fp32 accum.
// cp.async 3-stage pipeline; 2 CTAs/SM.
__global__ __launch_bounds__(256, 2) void simmma_kernel()
{
    __shared__ __align__(128) char sm[49152];   // 3 stages x (A 8KB | B 8KB); reused for scores
    const int tid = threadIdx.x;
    const int w = tid >> 5, l = tid & 31;
    const int b = blockIdx.y;

    // decode job -> (tt, jt)
    const int id = blockIdx.x;
    int tt = (int)((sqrtf(8.0f * (float)id + 1.0f) - 1.0f) * 0.5f);
    while ((tt + 1) * (tt + 2) / 2 <= id) ++tt;
    while (tt * (tt + 1) / 2 > id) --tt;
    const int jt = id - tt * (tt + 1) / 2;
    const int t0 = tt * TILE, j0 = jt * TILE;

    const int wm = (w >> 2) * 64;     // warp row offset (0 or 64)
    const int wn = (w & 3) * 32;      // warp col offset

    // ---- precompute swizzled ldmatrix byte offsets (within 8KB region) ----
    const int lr8 = l & 7;
    const int lb3 = (l >> 3) & 1;
    const int lb4 = (l >> 4) & 1;
    uint32_t aoff[4], boff[2];
#pragma unroll
    for (int mi = 0; mi < 4; ++mi) {
        const uint32_t row = (uint32_t)(wm + mi * 16 + lr8 + lb3 * 8);
        aoff[mi] = SW64(row * 64 + (uint32_t)lb4 * 16);
    }
#pragma unroll
    for (int n2 = 0; n2 < 2; ++n2) {
        const uint32_t row = (uint32_t)(wn + n2 * 16 + lb4 * 8 + lr8);
        boff[n2] = SW64(row * 64 + (uint32_t)lb3 * 16);
    }

    float acc[4][4][4];
#pragma unroll
    for (int mi = 0; mi < 4; ++mi)
#pragma unroll
        for (int ni = 0; ni < 4; ++ni)
#pragma unroll
            for (int q = 0; q < 4; ++q) acc[mi][ni][q] = 0.0f;

    const __nv_bfloat16* xb = g_xb + (size_t)b * NT * ND;
    const int r  = tid >> 1;              // row 0..127
    const int u0 = (tid & 1) * 2;         // first 16B unit within 64B row
    const uint32_t sb = smem_u32(sm);
    const uint32_t so0 = SW64((uint32_t)(r * 64 + u0 * 16));
    const uint32_t so1 = SW64((uint32_t)(r * 64 + (u0 + 1) * 16));
    const __nv_bfloat16* arow = xb + (size_t)(t0 + r) * ND + u0 * 8;
    const __nv_bfloat16* brow = xb + (size_t)(j0 + r) * ND + u0 * 8;

#define ISSUE(cc, pp) do {                                                      \
    const uint32_t aB_ = sb + (pp) * 16384;                                     \
    const __nv_bfloat16* as_ = arow + (cc) * KC;                                \
    const __nv_bfloat16* bs_ = brow + (cc) * KC;                                \
    CP_ASYNC16(aB_ + so0, as_);        CP_ASYNC16(aB_ + so1, as_ + 8);          \
    CP_ASYNC16(aB_ + 8192 + so0, bs_); CP_ASYNC16(aB_ + 8192 + so1, bs_ + 8);   \
    CP_COMMIT();                                                                \
} while (0)

    ISSUE(0, 0);
    ISSUE(1, 1);
#pragma unroll 1
    for (int c = 0; c < NCH; ++c) {
        const int p = c % 3;
        if (c + 1 < NCH) CP_WAIT(1); else CP_WAIT(0);
        __syncthreads();
        if (c + 2 < NCH) ISSUE(c + 2, (c + 2) % 3);
        const uint32_t aB = sb + p * 16384;
        const uint32_t bB = aB + 8192;
#pragma unroll
        for (int ks = 0; ks < 2; ++ks) {
            uint32_t af[4][4], bf[2][4];
#pragma unroll
            for (int mi = 0; mi < 4; ++mi)
                ldmatrix_x4(af[mi][0], af[mi][1], af[mi][2], af[mi][3],
                            aB + (aoff[mi] ^ (ks * 32)));
#pragma unroll
            for (int n2 = 0; n2 < 2; ++n2)
                ldmatrix_x4(bf[n2][0], bf[n2][1], bf[n2][2], bf[n2][3],
                            bB + (boff[n2] ^ (ks * 32)));
#pragma unroll
            for (int mi = 0; mi < 4; ++mi)
#pragma unroll
                for (int ni = 0; ni < 4; ++ni)
                    mma_bf16(acc[mi][ni][0], acc[mi][ni][1], acc[mi][ni][2], acc[mi][ni][3],
                             af[mi][0], af[mi][1], af[mi][2], af[mi][3],
                             bf[ni >> 1][(ni & 1) * 2], bf[ni >> 1][(ni & 1) * 2 + 1]);
        }
    }
#undef ISSUE

    // ---- epilogue: 4 column-chunks of 32, stage to smem, running top-12 ----
    const int g  = l >> 2;
    const int tg = l & 3;
    float* sc = (float*)sm;                 // [128][34] per chunk (17408 B)
    float tv[NCPT]; int tj[NCPT];
#pragma unroll
    for (int i = 0; i < NCPT; ++i) { tv[i] = -3.0e38f; tj[i] = 0; }
    const int myt = t0 + tid;               // row this thread scans (tid < 128)

#pragma unroll 1
    for (int ch = 0; ch < 4; ++ch) {
        __syncthreads();                    // prior reads done
        if ((w & 3) == ch) {
#pragma unroll
            for (int mi = 0; mi < 4; ++mi)
#pragma unroll
                for (int ni = 0; ni < 4; ++ni) {
                    const int colw = ni * 8 + tg * 2;
                    float* p0 = sc + (wm + mi * 16 + g) * 34 + colw;
                    float* p1 = sc + (wm + mi * 16 + g + 8) * 34 + colw;
                    p0[0] = acc[mi][ni][0]; p0[1] = acc[mi][ni][1];
                    p1[0] = acc[mi][ni][2]; p1[1] = acc[mi][ni][3];
                }
        }
        __syncthreads();
        if (tid < 128) {
            const float* rowp = sc + tid * 34;
            const int jb = j0 + ch * 32;
#pragma unroll 1
            for (int cix = 0; cix < 32; ++cix) {
                const float v = rowp[cix];
                const int   j = jb + cix;
                if (v > tv[NCPT - 1] && j < myt) {
                    tv[NCPT - 1] = v; tj[NCPT - 1] = j;
#pragma unroll
                    for (int q = NCPT - 1; q > 0; --q) {
                        if (tv[q] > tv[q - 1]) {
                            const float tf = tv[q]; tv[q] = tv[q - 1]; tv[q - 1] = tf;
                            const int   ii = tj[q]; tj[q] = tj[q - 1]; tj[q - 1] = ii;
                        }
                    }
                }
            }
        }
    }

    if (tid < 128) {
        const size_t base = ((size_t)(b * NT + myt) * 32 + jt) * NCPT;
#pragma unroll
        for (int i = 0; i < NCPT; ++i) { g_cv[base + i] = tv[i]; g_ci[base + i] = tj[i]; }
    }
}

// ============ Kernel: merge per-tile lists -> top-12 candidates =========
__global__ void merge_kernel()
{
    const int row = blockIdx.x * blockDim.x + threadIdx.x;
    if (row >= NB * NT) return;
    const int t  = row & (NT - 1);
    const int nl = (t >> 7) + 1;
    float bv[NCAND]; int bi[NCAND];
    for (int i = 0; i < NCAND; ++i) { bv[i] = -3.0e38f; bi[i] = 0; }
    for (int l = 0; l < nl; ++l) {
        const size_t base = ((size_t)row * 32 + l) * NCPT;
        for (int i = 0; i < NCPT; ++i) {
            const float v = g_cv[base + i];
            if (v <= bv[NCAND - 1]) break;          // lists sorted desc
            const int j = g_ci[base + i];
            int pos = NCAND - 1;
            while (pos > 0 && bv[pos - 1] < v) {
                bv[pos] = bv[pos - 1]; bi[pos] = bi[pos - 1]; --pos;
            }
            bv[pos] = v; bi[pos] = j;
        }
    }
    int m = 0;
    for (int i = 0; i < NCAND; ++i) {
        if (bv[i] > -1.0e30f) { g_cand[(size_t)row * NCAND + i] = bi[i]; ++m; }
    }
    g_cnt[row] = m;
}

// ===================== Kernel: q/k projection ===========================
__global__ __launch_bounds__(256) void qk_kernel(const float* __restrict__ x,
                                                 const float* __restrict__ Wq,
                                                 const float* __restrict__ Wk)
{
    const int row0 = blockIdx.x * 64;
    __shared__ float xs[16][64];
    __shared__ float ws[16][64];
    const int tid = threadIdx.x;
    const int ty = tid >> 4, tx = tid & 15;
    const int lr = tid >> 2;
    const int lk = (tid & 3) * 4;
    float acc[4][4];
#pragma unroll
    for (int i = 0; i < 4; ++i)
#pragma unroll
        for (int j = 0; j < 4; ++j) acc[i][j] = 0.0f;

    const float* Wrow = (lr < 32) ? (Wq + (size_t)lr * ND) : (Wk + (size_t)(lr - 32) * ND);
    for (int kd = 0; kd < ND; kd += 16) {
        const float4 xv = *(const float4*)(x + (size_t)(row0 + lr) * ND + kd + lk);
        const float4 wv = *(const float4*)(Wrow + kd + lk);
        __syncthreads();
        xs[lk + 0][lr] = xv.x; xs[lk + 1][lr] = xv.y; xs[lk + 2][lr] = xv.z; xs[lk + 3][lr] = xv.w;
        ws[lk + 0][lr] = wv.x; ws[lk + 1][lr] = wv.y; ws[lk + 2][lr] = wv.z; ws[lk + 3][lr] = wv.w;
        __syncthreads();
#pragma unroll
        for (int k = 0; k < 16; ++k) {
            const float4 a  = *(const float4*)&xs[k][4 * ty];
            const float4 w4 = *(const float4*)&ws[k][4 * tx];
            const float ar[4] = {a.x, a.y, a.z, a.w};
            const float br[4] = {w4.x, w4.y, w4.z, w4.w};
#pragma unroll
            for (int i = 0; i < 4; ++i)
#pragma unroll
                for (int j = 0; j < 4; ++j)
                    acc[i][j] = fmaf(ar[i], br[j], acc[i][j]);
        }
    }
#pragma unroll
    for (int i = 0; i < 4; ++i) {
        const int rw = row0 + 4 * ty + i;
#pragma unroll
        for (int j = 0; j < 4; ++j) {
            const int h = 4 * tx + j;
            if (h < 32) g_q[(size_t)rw * DH + h] = acc[i][j];
            else        g_k[(size_t)rw * DH + (h - 32)] = acc[i][j];
        }
    }
}

// ============== Kernels: deterministic 2-pass column mean ===============
__global__ void mean1_kernel(const float* __restrict__ x)
{
    const int b = blockIdx.y, z = blockIdx.z;
    const int lane = threadIdx.x & 31, g = threadIdx.x >> 5;
    const int c4 = blockIdx.x * 32 + lane;
    const float* xb = x + (size_t)b * NT * ND;
    float4 acc = {0.f, 0.f, 0.f, 0.f};
    for (int r = z * 256 + g; r < z * 256 + 256; r += 8) {
        const float4 v = *(const float4*)(xb + (size_t)r * ND + 4 * c4);
        acc.x += v.x; acc.y += v.y; acc.z += v.z; acc.w += v.w;
    }
    __shared__ float4 red[8][32];
    red[g][lane] = acc;
    __syncthreads();
    if (g == 0) {
        float4 sm = red[0][lane];
        for (int q = 1; q < 8; ++q) {
            const float4 v = red[q][lane];
            sm.x += v.x; sm.y += v.y; sm.z += v.z; sm.w += v.w;
        }
        *(float4*)(g_meanp + ((size_t)z * NB + b) * ND + 4 * c4) = sm;
    }
}
__global__ void mean2_kernel()
{
    const int idx = blockIdx.x * blockDim.x + threadIdx.x;
    if (idx >= NB * ND) return;
    const int b = idx / ND, d = idx % ND;
    float s = 0.0f;
    for (int z = 0; z < 16; ++z) s += g_meanp[((size_t)z * NB + b) * ND + d];
    g_mean[b * ND + d] = s * (1.0f / (float)NT);
}

// ====== Kernel: fused exact fp32 re-rank + scores/softmax/msg/GELU ======
// One block (256 threads) per row.
__global__ __launch_bounds__(256) void finish_kernel(const float* __restrict__ x,
                                                     const float* __restrict__ gain,
                                                     const float* __restrict__ bias,
                                                     const float* __restrict__ p_lm,
                                                     const float* __restrict__ p_ls,
                                                     float* __restrict__ out)
{
    const int row = blockIdx.x;
    const int b = row >> 12;
    const int t = row & (NT - 1);
    const int tid = threadIdx.x, wid = tid >> 5, lane = tid & 31;

    const float mix   = 1.0f / (1.0f + expf(-p_lm[0]));
    const float scale = log1pf(expf(p_ls[0])) + 0.01f;

    __shared__ float sval[NCAND];
    __shared__ int   scand[NCAND];
    __shared__ float w8[KTOP];
    __shared__ int   jj[KTOP];

    const int m  = g_cnt[row];
    const int kk = m < KTOP ? m : KTOP;

    if (m > 0) {
        if (tid < m) scand[tid] = g_cand[(size_t)row * NCAND + tid];
        __syncthreads();

        // exact fp32 sim re-rank: one warp per candidate
        const float4* qa = (const float4*)(x + (size_t)(b * NT + t) * ND);
#pragma unroll 1
        for (int cc = wid; cc < m; cc += 8) {
            const int j = scand[cc];
            const float4* ka = (const float4*)(x + (size_t)(b * NT + j) * ND);
            float s = 0.0f;
#pragma unroll
            for (int i = 0; i < 8; ++i) {
                const float4 q4 = qa[i * 32 + lane];
                const float4 k4 = ka[i * 32 + lane];
                s = fmaf(q4.x, k4.x, s); s = fmaf(q4.y, k4.y, s);
                s = fmaf(q4.z, k4.z, s); s = fmaf(q4.w, k4.w, s);
            }
#pragma unroll
            for (int o = 16; o > 0; o >>= 1) s += __shfl_xor_sync(0xffffffffu, s, o);
            if (lane == 0) sval[cc] = s;
        }
        __syncthreads();
        if (tid == 0) {
            bool usedf[NCAND];
            for (int i = 0; i < m; ++i) usedf[i] = false;
            for (int rr = 0; rr < kk; ++rr) {
                int best = -1; float bvv = -3.4e38f;
                for (int i = 0; i < m; ++i)
                    if (!usedf[i] && sval[i] > bvv) { bvv = sval[i]; best = i; }
                usedf[best] = true;
                jj[rr] = scand[best];
            }
        }
        __syncthreads();

        // attention scores on the top-kk neighbors
        if (tid < kk) {
            const int j = jj[tid];
            const float* qv = g_q + (size_t)row * DH;
            const float* kv = g_k + ((size_t)b * NT + j) * DH;
            float sc = 0.0f;
#pragma unroll
            for (int h = 0; h < DH; ++h) sc = fmaf(qv[h], kv[h], sc);
            w8[tid] = sc * 0.17677669529663687f;   // 1/sqrt(32)
        }
        __syncthreads();
        if (tid == 0) {
            float mx = w8[0];
            for (int i = 1; i < kk; ++i) mx = fmaxf(mx, w8[i]);
            float sum = 0.0f;
            for (int i = 0; i < kk; ++i) { const float e = expf(w8[i] - mx); w8[i] = e; sum += e; }
            const float inv = 1.0f / sum;
            for (int i = 0; i < kk; ++i) w8[i] *= inv;
        }
        __syncthreads();
    }

    const int d0 = 4 * tid;
    float4 msg;
    if (m > 0) {
        float4 a = {0.f, 0.f, 0.f, 0.f};
        for (int i = 0; i < kk; ++i) {
            const float wi = w8[i];
            const float4 xv = *(const float4*)(x + ((size_t)b * NT + jj[i]) * ND + d0);
            a.x = fmaf(wi, xv.x, a.x);
            a.y = fmaf(wi, xv.y, a.y);
            a.z = fmaf(wi, xv.z, a.z);
            a.w = fmaf(wi, xv.w, a.w);
        }
        msg = a;
    } else {
        msg = *(const float4*)(g_mean + b * ND + d0);   // t==0: uniform over all T
    }

    const float4 xt = *(const float4*)(x + (size_t)row * ND + d0);
    const float4 gn = *(const float4*)(gain + d0);
    const float4 bs = *(const float4*)(bias + d0);
    const float om = 1.0f - mix;
    float4 o;
#define GEL(c) { float z = mix * xt.c + om * msg.c;                         \
                 z = fmaf(z, gn.c, bs.c);                                   \
                 o.c = 0.5f * z * (1.0f + erff(z * 0.7071067811865476f)) * scale; }
    GEL(x) GEL(y) GEL(z) GEL(w)
#undef GEL
    *(float4*)(out + (size_t)row * ND + d0) = o;
}

// =========================================================================
extern "C" void kernel_launch(void* const* d_in, const int* in_sizes, int n_in,
                              void* d_out, int out_size)
{
    (void)in_sizes; (void)n_in; (void)out_size;
    const float* x    = (const float*)d_in[0];
    const float* Wq   = (const float*)d_in[1];
    const float* Wk   = (const float*)d_in[2];
    const float* gain = (const float*)d_in[3];
    const float* bias = (const float*)d_in[4];
    const float* lm   = (const float*)d_in[5];
    const float* ls   = (const float*)d_in[6];
    float* out = (float*)d_out;

    xcvt_kernel<<<NB * NT * ND / 4 / 256, 256>>>(x);
    qk_kernel<<<NB * NT / 64, 256>>>(x, Wq, Wk);
    mean1_kernel<<<dim3(8, NB, 16), 256>>>(x);
    simmma_kernel<<<dim3(528, NB), 256>>>();
    mean2_kernel<<<(NB * ND + 255) / 256, 256>>>();
    merge_kernel<<<(NB * NT + 255) / 256, 256>>>();
    finish_kernel<<<NB * NT, 256>>>(x, gain, bias, lm, ls, out);
}